// round 17
// baseline (speedup 1.0000x reference)
#include <cuda_runtime.h>
#include <cuda_bf16.h>
#include <cstdint>

#define T_TOK 16384
#define H_DIM 1024
#define I_DIM 2048
#define N_EXP 16
#define NROWS (T_TOK * 2)
#define MAXTILES 288

// ---------------- routing scratch ----------------
__device__ int   g_count[N_EXP];
__device__ int   g_cursor[N_EXP];
__device__ int   g_offset[N_EXP + 1];
__device__ int   g_ntiles;
__device__ int   g_tile_e[MAXTILES];
__device__ int   g_tile_bm[MAXTILES];
__device__ int   g_e0[T_TOK];
__device__ int   g_e1[T_TOK];
__device__ float g_w0[T_TOK];
__device__ float g_w1[T_TOK];
__device__ int   g_token_of_row[NROWS];
__device__ float g_w_of_row[NROWS];

// ---------------- data buffers ----------------
// weights kept in NATIVE [E][K][N] layout, split hi/lo (no transpose)
__device__ __nv_bfloat16 g_xh[(size_t)NROWS * H_DIM];
__device__ __nv_bfloat16 g_xl[(size_t)NROWS * H_DIM];
__device__ __nv_bfloat16 g_wgh[(size_t)N_EXP * H_DIM * I_DIM];
__device__ __nv_bfloat16 g_wgl[(size_t)N_EXP * H_DIM * I_DIM];
__device__ __nv_bfloat16 g_wuh[(size_t)N_EXP * H_DIM * I_DIM];
__device__ __nv_bfloat16 g_wul[(size_t)N_EXP * H_DIM * I_DIM];
__device__ __nv_bfloat16 g_wdh[(size_t)N_EXP * I_DIM * H_DIM];
__device__ __nv_bfloat16 g_wdl[(size_t)N_EXP * I_DIM * H_DIM];
__device__ __nv_bfloat16 g_hh[(size_t)NROWS * I_DIM];
__device__ __nv_bfloat16 g_hl[(size_t)NROWS * I_DIM];

// ---------------- ptx helpers ----------------
__device__ __forceinline__ uint32_t smem_u32(const void* p) {
    uint32_t a;
    asm("{ .reg .u64 t; cvta.to.shared.u64 t, %1; cvt.u32.u64 %0, t; }" : "=r"(a) : "l"(p));
    return a;
}
__device__ __forceinline__ void cp16(uint32_t dst, const void* src, uint32_t sz) {
    asm volatile("cp.async.cg.shared.global [%0], [%1], 16, %2;"
                 :: "r"(dst), "l"(src), "r"(sz));
}
__device__ __forceinline__ void ldm_x4(uint32_t a, uint32_t r[4]) {
    asm volatile("ldmatrix.sync.aligned.m8n8.x4.shared.b16 {%0,%1,%2,%3}, [%4];"
                 : "=r"(r[0]), "=r"(r[1]), "=r"(r[2]), "=r"(r[3]) : "r"(a));
}
__device__ __forceinline__ void ldm_x4t(uint32_t a, uint32_t r[4]) {
    asm volatile("ldmatrix.sync.aligned.m8n8.x4.trans.shared.b16 {%0,%1,%2,%3}, [%4];"
                 : "=r"(r[0]), "=r"(r[1]), "=r"(r[2]), "=r"(r[3]) : "r"(a));
}
__device__ __forceinline__ void mma_bf16(float* c, const uint32_t* a, const uint32_t* b) {
    asm volatile(
        "mma.sync.aligned.m16n8k16.row.col.f32.bf16.bf16.f32 "
        "{%0,%1,%2,%3}, {%4,%5,%6,%7}, {%8,%9}, {%0,%1,%2,%3};"
        : "+f"(c[0]), "+f"(c[1]), "+f"(c[2]), "+f"(c[3])
        : "r"(a[0]), "r"(a[1]), "r"(a[2]), "r"(a[3]), "r"(b[0]), "r"(b[1]));
}
__device__ __forceinline__ void red_add(float* p, float v) {
    asm volatile("red.global.add.f32 [%0], %1;" :: "l"(p), "f"(v) : "memory");
}

// ---------------- small kernels (routing path) ----------------
__global__ void zero_kernel() {
    int i = threadIdx.x;
    if (i < N_EXP) { g_count[i] = 0; g_cursor[i] = 0; }
}

// zero the output buffer (out is poisoned before timing; down REDs into it)
__global__ void zero_out_kernel(float4* __restrict__ out) {
    size_t i = (size_t)blockIdx.x * blockDim.x + threadIdx.x;
    size_t stride = (size_t)gridDim.x * blockDim.x;
    size_t n = (size_t)T_TOK * H_DIM / 4;
    float4 z = make_float4(0.f, 0.f, 0.f, 0.f);
    for (; i < n; i += stride) out[i] = z;
}

// router v2: lane = (k-octant kk, expert-quad eq); float4 loads, 16 FMA/step;
// butterfly over kk, shuffle-gather quads, per-lane top-2 (strict > = lowest-index ties)
__global__ void router_kernel(const float* __restrict__ x, const float* __restrict__ wg) {
    int warp = (blockIdx.x * blockDim.x + threadIdx.x) >> 5;
    int lane = threadIdx.x & 31;
    if (warp >= T_TOK) return;
    const int t  = warp;
    const int kk = lane >> 2;      // 0..7
    const int eq = lane & 3;       // 0..3  (experts eq*4 .. eq*4+3)

    const float4* xr = (const float4*)(x + (size_t)t * H_DIM);
    float4 acc = make_float4(0.f, 0.f, 0.f, 0.f);

    #pragma unroll 4
    for (int j = 0; j < 32; j++) {
        int k4 = j * 32 + kk * 4;
        float4 xv = xr[k4 >> 2];
        const float4* wp = (const float4*)(wg + (size_t)k4 * N_EXP + eq * 4);
        float4 w0 = wp[0];
        float4 w1 = wp[4];
        float4 w2 = wp[8];
        float4 w3 = wp[12];
        acc.x += xv.x * w0.x + xv.y * w1.x + xv.z * w2.x + xv.w * w3.x;
        acc.y += xv.x * w0.y + xv.y * w1.y + xv.z * w2.y + xv.w * w3.y;
        acc.z += xv.x * w0.z + xv.y * w1.z + xv.z * w2.z + xv.w * w3.z;
        acc.w += xv.x * w0.w + xv.y * w1.w + xv.z * w2.w + xv.w * w3.w;
    }

    #pragma unroll
    for (int s = 4; s < 32; s <<= 1) {
        acc.x += __shfl_xor_sync(0xffffffffu, acc.x, s);
        acc.y += __shfl_xor_sync(0xffffffffu, acc.y, s);
        acc.z += __shfl_xor_sync(0xffffffffu, acc.z, s);
        acc.w += __shfl_xor_sync(0xffffffffu, acc.w, s);
    }

    float lg[16];
    #pragma unroll
    for (int q = 0; q < 4; q++) {
        lg[q * 4 + 0] = __shfl_sync(0xffffffffu, acc.x, q);
        lg[q * 4 + 1] = __shfl_sync(0xffffffffu, acc.y, q);
        lg[q * 4 + 2] = __shfl_sync(0xffffffffu, acc.z, q);
        lg[q * 4 + 3] = __shfl_sync(0xffffffffu, acc.w, q);
    }

    if (lane == 0) {
        float l1 = -1e30f; int i1 = 0;
        #pragma unroll
        for (int e = 0; e < N_EXP; e++)
            if (lg[e] > l1) { l1 = lg[e]; i1 = e; }
        float l2 = -1e30f; int i2 = 0;
        #pragma unroll
        for (int e = 0; e < N_EXP; e++)
            if (e != i1 && lg[e] > l2) { l2 = lg[e]; i2 = e; }

        float r  = __expf(l2 - l1);
        float w0 = 1.f / (1.f + r);
        g_e0[t] = i1; g_e1[t] = i2;
        g_w0[t] = w0; g_w1[t] = 1.f - w0;
        atomicAdd(&g_count[i1], 1);
        atomicAdd(&g_count[i2], 1);
    }
}

// scan + build exact tile map (<= 272 live m-tiles)
__global__ void scan_kernel() {
    if (threadIdx.x == 0) {
        int o = 0, tt = 0;
        for (int e = 0; e < N_EXP; e++) {
            g_offset[e] = o;
            int cnt = g_count[e];
            for (int bm = 0; bm < cnt; bm += 128) {
                g_tile_e[tt] = e; g_tile_bm[tt] = bm; tt++;
            }
            o += cnt;
        }
        g_offset[N_EXP] = o;
        g_ntiles = tt;
    }
}

// merged assign + gather: 1 warp per token. Lane 0 claims both rows,
// warp splits x[t] to bf16 hi/lo ONCE and stores to both destination rows.
__global__ void assign_gather_kernel(const float* __restrict__ x) {
    int warp = (blockIdx.x * blockDim.x + threadIdx.x) >> 5;
    int lane = threadIdx.x & 31;
    if (warp >= T_TOK) return;
    const int t = warp;

    int r0 = 0, r1 = 0;
    if (lane == 0) {
        int e0 = g_e0[t];
        r0 = g_offset[e0] + atomicAdd(&g_cursor[e0], 1);
        g_token_of_row[r0] = t; g_w_of_row[r0] = g_w0[t];
        int e1 = g_e1[t];
        r1 = g_offset[e1] + atomicAdd(&g_cursor[e1], 1);
        g_token_of_row[r1] = t; g_w_of_row[r1] = g_w1[t];
    }
    r0 = __shfl_sync(0xffffffffu, r0, 0);
    r1 = __shfl_sync(0xffffffffu, r1, 0);

    const float4* src = (const float4*)(x + (size_t)t * H_DIM);
    __nv_bfloat16* dh0 = g_xh + (size_t)r0 * H_DIM;
    __nv_bfloat16* dl0 = g_xl + (size_t)r0 * H_DIM;
    __nv_bfloat16* dh1 = g_xh + (size_t)r1 * H_DIM;
    __nv_bfloat16* dl1 = g_xl + (size_t)r1 * H_DIM;

    #pragma unroll
    for (int it = 0; it < 8; it++) {
        int i = lane + it * 32;               // 0..255 float4 chunks
        float4 v = src[i];
        __nv_bfloat16 h0 = __float2bfloat16(v.x);
        __nv_bfloat16 h1 = __float2bfloat16(v.y);
        __nv_bfloat16 h2 = __float2bfloat16(v.z);
        __nv_bfloat16 h3 = __float2bfloat16(v.w);
        __nv_bfloat162 ph0(h0, h1), ph1(h2, h3);
        __nv_bfloat162 pl0(__float2bfloat16(v.x - __bfloat162float(h0)),
                           __float2bfloat16(v.y - __bfloat162float(h1)));
        __nv_bfloat162 pl1(__float2bfloat16(v.z - __bfloat162float(h2)),
                           __float2bfloat16(v.w - __bfloat162float(h3)));
        uint2 uh, ul;
        uh.x = *(uint32_t*)&ph0; uh.y = *(uint32_t*)&ph1;
        ul.x = *(uint32_t*)&pl0; ul.y = *(uint32_t*)&pl1;
        *(uint2*)(dh0 + i * 4) = uh; *(uint2*)(dl0 + i * 4) = ul;
        *(uint2*)(dh1 + i * 4) = uh; *(uint2*)(dl1 + i * 4) = ul;
    }
}

// streaming hi/lo split helpers
__device__ __forceinline__ void split4(float4 v, uint2& uh, uint2& ul) {
    __nv_bfloat16 h0 = __float2bfloat16(v.x);
    __nv_bfloat16 h1 = __float2bfloat16(v.y);
    __nv_bfloat16 h2 = __float2bfloat16(v.z);
    __nv_bfloat16 h3 = __float2bfloat16(v.w);
    __nv_bfloat162 ph0(h0, h1), ph1(h2, h3);
    __nv_bfloat162 pl0(__float2bfloat16(v.x - __bfloat162float(h0)),
                       __float2bfloat16(v.y - __bfloat162float(h1)));
    __nv_bfloat162 pl1(__float2bfloat16(v.z - __bfloat162float(h2)),
                       __float2bfloat16(v.w - __bfloat162float(h3)));
    uh.x = *(uint32_t*)&ph0; uh.y = *(uint32_t*)&ph1;
    ul.x = *(uint32_t*)&pl0; ul.y = *(uint32_t*)&pl1;
}

// gate+up weight split (stream s1; feeds gateup GEMM)
__global__ void split_w_gu(const float4* __restrict__ w0, const float4* __restrict__ w1, int n4) {
    int z = blockIdx.z;
    const float4* src = (z == 0) ? w0 : w1;
    uint2* dh = (z == 0) ? (uint2*)g_wgh : (uint2*)g_wuh;
    uint2* dl = (z == 0) ? (uint2*)g_wgl : (uint2*)g_wul;
    int i = blockIdx.x * blockDim.x + threadIdx.x;
    int stride = gridDim.x * blockDim.x;
    for (; i < n4; i += stride) {
        uint2 uh, ul;
        split4(src[i], uh, ul);
        dh[i] = uh; dl[i] = ul;
    }
}

// down weight split (stream s2; feeds down GEMM — overlaps with gateup)
__global__ void split_w_d(const float4* __restrict__ w2, int n4) {
    int i = blockIdx.x * blockDim.x + threadIdx.x;
    int stride = gridDim.x * blockDim.x;
    uint2* dh = (uint2*)g_wdh;
    uint2* dl = (uint2*)g_wdl;
    for (; i < n4; i += stride) {
        uint2 uh, ul;
        split4(w2[i], uh, ul);
        dh[i] = uh; dl[i] = ul;
    }
}

// ============================================================================
// bf16x3 grouped GEMMs on mma.sync. Flattened tile-map grid.
// A tiles: 128B rows, swizzle: chunk c of row r at r*128+((c^(r&7))<<4)
// B tiles: 256B rows, swizzle: chunk c of row r at r*256+((c^(r&7))<<4)
// B consumed with ldmatrix.x4.trans (weights in native [K][N] layout).
// ============================================================================
#define STAGE_F  98304   // gateup BK=64: Ah,Al (16K) + Gh,Gl,Uh,Ul (16K); 2 stages, occ 1
#define STAGE_D  49152   // down  BK=32: Ah,Al (16K, half-filled rows) + Bh,Bl (8K); 2 stages, occ 2
#define SMEM_F   (2 * STAGE_F)
#define SMEM_D   (2 * STAGE_D)

__device__ __forceinline__ void load_A(uint32_t sb, int tid, const __nv_bfloat16* src,
                                       size_t rstride, int k0, int valid) {
    #pragma unroll
    for (int j = 0; j < 4; j++) {
        int u = tid + j * 256;              // 0..1023
        int r = u >> 3, c = u & 7;
        uint32_t off = (uint32_t)(r * 128 + ((c ^ (r & 7)) << 4));
        cp16(sb + off, src + (size_t)r * rstride + k0 + c * 8, (r < valid) ? 16u : 0u);
    }
}
// BK=32 A loader: 128B rows, only chunks 0..3 live (k 0..31)
__device__ __forceinline__ void load_A32(uint32_t sb, int tid, const __nv_bfloat16* src,
                                         size_t rstride, int k0, int valid) {
    #pragma unroll
    for (int j = 0; j < 2; j++) {
        int u = tid + j * 256;              // 0..511
        int r = u >> 2, c = u & 3;
        uint32_t off = (uint32_t)(r * 128 + ((c ^ (r & 7)) << 4));
        cp16(sb + off, src + (size_t)r * rstride + k0 + c * 8, (r < valid) ? 16u : 0u);
    }
}
__device__ __forceinline__ void load_B(uint32_t sb, int tid, const __nv_bfloat16* src,
                                       size_t N, int k0) {
    #pragma unroll
    for (int j = 0; j < 4; j++) {
        int u = tid + j * 256;
        int r = u >> 4, c = u & 15;         // r: 0..63 (k), c: 16B n-chunk
        uint32_t off = (uint32_t)(r * 256 + ((c ^ (r & 7)) << 4));
        cp16(sb + off, src + (size_t)(k0 + r) * N + c * 8, 16u);
    }
}
// BK=32 B loader: 32 k-rows
__device__ __forceinline__ void load_B32(uint32_t sb, int tid, const __nv_bfloat16* src,
                                         size_t N, int k0) {
    #pragma unroll
    for (int j = 0; j < 2; j++) {
        int u = tid + j * 256;              // 0..511
        int r = u >> 4, c = u & 15;         // r: 0..31
        uint32_t off = (uint32_t)(r * 256 + ((c ^ (r & 7)) << 4));
        cp16(sb + off, src + (size_t)(k0 + r) * N + c * 8, 16u);
    }
}

// load hi+lo B fragments for 4 n8-tiles via 4 x ldmatrix.x4.trans
__device__ __forceinline__ void load_bfrags(uint32_t sb, uint32_t boff, uint32_t lo_delta,
                                            int wn, uint32_t broff, uint32_t bxor,
                                            int lane, uint32_t bh[4][2], uint32_t bl[4][2]) {
    #pragma unroll
    for (int ntp = 0; ntp < 2; ntp++) {
        uint32_t ch = (uint32_t)(wn * 4 + ntp * 2 + (lane >> 4)) ^ bxor;
        uint32_t ad = sb + boff + broff + (ch << 4);
        uint32_t r4[4];
        ldm_x4t(ad, r4);
        bh[2 * ntp][0] = r4[0]; bh[2 * ntp][1] = r4[1];
        bh[2 * ntp + 1][0] = r4[2]; bh[2 * ntp + 1][1] = r4[3];
        ldm_x4t(ad + lo_delta, r4);
        bl[2 * ntp][0] = r4[0]; bl[2 * ntp][1] = r4[1];
        bl[2 * ntp + 1][0] = r4[2]; bl[2 * ntp + 1][1] = r4[3];
    }
}

// ---------------- fused gate+up: h = up(x) * silu(gate(x)) -> bf16 hi/lo ----------------
__global__ __launch_bounds__(256, 1) void moe_gateup_kernel() {
    constexpr int KD = H_DIM, NCH = KD / 64;

    const int tile = blockIdx.y;
    if (tile >= g_ntiles) return;
    const int e    = g_tile_e[tile];
    const int bm   = g_tile_bm[tile];
    const int m0   = g_offset[e];
    const int rows = g_offset[e + 1] - m0;
    const int bn   = blockIdx.x * 128;
    const int va   = min(rows - bm, 128);

    extern __shared__ char smem[];
    const uint32_t sbase = smem_u32(smem);
    const int tid = threadIdx.x;
    const int lane = tid & 31, wid = tid >> 5;
    const int wm = wid >> 2, wn = wid & 3;

    const __nv_bfloat16* Ah = g_xh + (size_t)(m0 + bm) * KD;
    const __nv_bfloat16* Al = g_xl + (size_t)(m0 + bm) * KD;
    const __nv_bfloat16* Gh = g_wgh + (size_t)e * KD * I_DIM + bn;
    const __nv_bfloat16* Gl = g_wgl + (size_t)e * KD * I_DIM + bn;
    const __nv_bfloat16* Uh = g_wuh + (size_t)e * KD * I_DIM + bn;
    const __nv_bfloat16* Ul = g_wul + (size_t)e * KD * I_DIM + bn;

    float accg[4][4][4], accu[4][4][4];
    #pragma unroll
    for (int i = 0; i < 4; i++)
        #pragma unroll
        for (int j = 0; j < 4; j++)
            #pragma unroll
            for (int k = 0; k < 4; k++) { accg[i][j][k] = 0.f; accu[i][j][k] = 0.f; }

    auto issue = [&](int c) {
        uint32_t sb = sbase + (uint32_t)(c & 1) * STAGE_F;
        int k0 = c * 64;
        load_A(sb,         tid, Ah, KD, k0, va);
        load_A(sb + 16384, tid, Al, KD, k0, va);
        load_B(sb + 32768, tid, Gh, I_DIM, k0);
        load_B(sb + 49152, tid, Gl, I_DIM, k0);
        load_B(sb + 65536, tid, Uh, I_DIM, k0);
        load_B(sb + 81920, tid, Ul, I_DIM, k0);
        asm volatile("cp.async.commit_group;");
    };

    issue(0);

    for (int c = 0; c < NCH; c++) {
        asm volatile("cp.async.wait_group 0;");
        __syncthreads();
        if (c + 1 < NCH) issue(c + 1);

        const uint32_t sb = sbase + (uint32_t)(c & 1) * STAGE_F;
        #pragma unroll
        for (int s16 = 0; s16 < 4; s16++) {
            // A fragments (hi, lo)
            uint32_t af[2][4][4];
            #pragma unroll
            for (int mt = 0; mt < 4; mt++) {
                int row = wm * 64 + mt * 16 + (lane & 15);
                uint32_t ch = (uint32_t)(2 * s16 + (lane >> 4)) ^ (uint32_t)(row & 7);
                uint32_t ad = sb + (uint32_t)(row * 128) + (ch << 4);
                ldm_x4(ad,         af[0][mt]);
                ldm_x4(ad + 16384, af[1][mt]);
            }
            const int rowb = s16 * 16 + (lane & 15);
            const uint32_t broff = (uint32_t)(rowb * 256);
            const uint32_t bxor  = (uint32_t)(rowb & 7);

            uint32_t bh[4][2], bl[4][2];
            // ---- gate ----
            load_bfrags(sb, 32768, 16384, wn, broff, bxor, lane, bh, bl);
            #pragma unroll
            for (int mt = 0; mt < 4; mt++)
                #pragma unroll
                for (int nt = 0; nt < 4; nt++) mma_bf16(accg[mt][nt], af[0][mt], bh[nt]);
            #pragma unroll
            for (int mt = 0; mt < 4; mt++)
                #pragma unroll
                for (int nt = 0; nt < 4; nt++) mma_bf16(accg[mt][nt], af[0][mt], bl[nt]);
            #pragma unroll
            for (int mt = 0; mt < 4; mt++)
                #pragma unroll
                for (int nt = 0; nt < 4; nt++) mma_bf16(accg[mt][nt], af[1][mt], bh[nt]);
            // ---- up ----
            load_bfrags(sb, 65536, 16384, wn, broff, bxor, lane, bh, bl);
            #pragma unroll
            for (int mt = 0; mt < 4; mt++)
                #pragma unroll
                for (int nt = 0; nt < 4; nt++) mma_bf16(accu[mt][nt], af[0][mt], bh[nt]);
            #pragma unroll
            for (int mt = 0; mt < 4; mt++)
                #pragma unroll
                for (int nt = 0; nt < 4; nt++) mma_bf16(accu[mt][nt], af[0][mt], bl[nt]);
            #pragma unroll
            for (int mt = 0; mt < 4; mt++)
                #pragma unroll
                for (int nt = 0; nt < 4; nt++) mma_bf16(accu[mt][nt], af[1][mt], bh[nt]);
        }
    }

    // epilogue: h = u*silu(g) in registers -> bf16 hi/lo
    const int lr = lane >> 2;
    const int lc = (lane & 3) * 2;
    #pragma unroll
    for (int mt = 0; mt < 4; mt++) {
        #pragma unroll
        for (int h2 = 0; h2 < 2; h2++) {
            int r = wm * 64 + mt * 16 + lr + h2 * 8;
            if (r < va) {
                size_t grow = (size_t)(m0 + bm + r);
                #pragma unroll
                for (int nt = 0; nt < 4; nt++) {
                    int col = wn * 32 + nt * 8 + lc;
                    float g0 = accg[mt][nt][h2 * 2], g1 = accg[mt][nt][h2 * 2 + 1];
                    float u0 = accu[mt][nt][h2 * 2], u1 = accu[mt][nt][h2 * 2 + 1];
                    float hv0 = u0 * g0 * __frcp_rn(1.f + __expf(-g0));
                    float hv1 = u1 * g1 * __frcp_rn(1.f + __expf(-g1));
                    __nv_bfloat16 hh0 = __float2bfloat16(hv0);
                    __nv_bfloat16 hh1 = __float2bfloat16(hv1);
                    __nv_bfloat16 hl0 = __float2bfloat16(hv0 - __bfloat162float(hh0));
                    __nv_bfloat16 hl1 = __float2bfloat16(hv1 - __bfloat162float(hh1));
                    *(__nv_bfloat162*)(g_hh + grow * I_DIM + bn + col) = __nv_bfloat162(hh0, hh1);
                    *(__nv_bfloat162*)(g_hl + grow * I_DIM + bn + col) = __nv_bfloat162(hl0, hl1);
                }
            }
        }
    }
}

// ---------------- down-proj + combine: out[t] += (h @ wd) * w  [BK=32, occ 2] ----------------
__global__ __launch_bounds__(256, 2) void moe_down_kernel(float* __restrict__ out) {
    constexpr int KD = I_DIM, ND = H_DIM, NCH = KD / 32;

    const int tile = blockIdx.y;
    if (tile >= g_ntiles) return;
    const int e    = g_tile_e[tile];
    const int bm   = g_tile_bm[tile];
    const int m0   = g_offset[e];
    const int rows = g_offset[e + 1] - m0;
    const int bn   = blockIdx.x * 128;
    const int va   = min(rows - bm, 128);

    extern __shared__ char smem[];
    const uint32_t sbase = smem_u32(smem);
    const int tid = threadIdx.x;
    const int lane = tid & 31, wid = tid >> 5;
    const int wm = wid >> 2, wn = wid & 3;

    const __nv_bfloat16* Ah = g_hh + (size_t)(m0 + bm) * KD;
    const __nv_bfloat16* Al = g_hl + (size_t)(m0 + bm) * KD;
    const __nv_bfloat16* Bh = g_wdh + (size_t)e * KD * ND + bn;
    const __nv_bfloat16* Bl = g_wdl + (size_t)e * KD * ND + bn;

    float acc[4][4][4];
    #pragma unroll
    for (int i = 0; i < 4; i++)
        #pragma unroll
        for (int j = 0; j < 4; j++)
            #pragma unroll
            for (int k = 0; k < 4; k++) acc[i][j][k] = 0.f;

    auto issue = [&](int c) {
        uint32_t sb = sbase + (uint32_t)(c & 1) * STAGE_D;
        int k0 = c * 32;
        load_A32(sb,         tid, Ah, KD, k0, va);
        load_A32(sb + 16384, tid, Al, KD, k0, va);
        load_B32(sb + 32768, tid, Bh, ND, k0);
        load_B32(sb + 40960, tid, Bl, ND, k0);
        asm volatile("cp.async.commit_group;");
    };

    issue(0);

    for (int c = 0; c < NCH; c++) {
        asm volatile("cp.async.wait_group 0;");
        __syncthreads();
        if (c + 1 < NCH) issue(c + 1);

        const uint32_t sb = sbase + (uint32_t)(c & 1) * STAGE_D;
        #pragma unroll
        for (int s16 = 0; s16 < 2; s16++) {
            // single A-frag buffer, reused hi -> lo (register diet for occ 2)
            uint32_t af[4][4];
            #pragma unroll
            for (int mt = 0; mt < 4; mt++) {
                int row = wm * 64 + mt * 16 + (lane & 15);
                uint32_t ch = (uint32_t)(2 * s16 + (lane >> 4)) ^ (uint32_t)(row & 7);
                ldm_x4(sb + (uint32_t)(row * 128) + (ch << 4), af[mt]);
            }
            const int rowb = s16 * 16 + (lane & 15);
            const uint32_t broff = (uint32_t)(rowb * 256);
            const uint32_t bxor  = (uint32_t)(rowb & 7);

            uint32_t bh[4][2], bl[4][2];
            load_bfrags(sb, 32768, 8192, wn, broff, bxor, lane, bh, bl);
            #pragma unroll
            for (int mt = 0; mt < 4; mt++)
                #pragma unroll
                for (int nt = 0; nt < 4; nt++) mma_bf16(acc[mt][nt], af[mt], bh[nt]);
            #pragma unroll
            for (int mt = 0; mt < 4; mt++)
                #pragma unroll
                for (int nt = 0; nt < 4; nt++) mma_bf16(acc[mt][nt], af[mt], bl[nt]);
            // overwrite A-frags with lo
            #pragma unroll
            for (int mt = 0; mt < 4; mt++) {
                int row = wm * 64 + mt * 16 + (lane & 15);
                uint32_t ch = (uint32_t)(2 * s16 + (lane >> 4)) ^ (uint32_t)(row & 7);
                ldm_x4(sb + 16384 + (uint32_t)(row * 128) + (ch << 4), af[mt]);
            }
            #pragma unroll
            for (int mt = 0; mt < 4; mt++)
                #pragma unroll
                for (int nt = 0; nt < 4; nt++) mma_bf16(acc[mt][nt], af[mt], bh[nt]);
        }
    }

    // epilogue: scale by routing weight and RED directly into out[token]
    // (each out element receives exactly 2 contributions onto 0.0; fp add is
    // commutative, so replay order cannot change the result)
    const int lr = lane >> 2;
    const int lc = (lane & 3) * 2;
    #pragma unroll
    for (int mt = 0; mt < 4; mt++) {
        #pragma unroll
        for (int h2 = 0; h2 < 2; h2++) {
            int r = wm * 64 + mt * 16 + lr + h2 * 8;
            if (r < va) {
                size_t grow = (size_t)(m0 + bm + r);
                float scale = g_w_of_row[grow];
                int tok = g_token_of_row[grow];
                float* C = out + (size_t)tok * ND + bn;
                #pragma unroll
                for (int nt = 0; nt < 4; nt++) {
                    int col = wn * 32 + nt * 8 + lc;
                    red_add(C + col,     acc[mt][nt][h2 * 2]     * scale);
                    red_add(C + col + 1, acc[mt][nt][h2 * 2 + 1] * scale);
                }
            }
        }
    }
}

// ---------------- launch ----------------
extern "C" void kernel_launch(void* const* d_in, const int* in_sizes, int n_in,
                              void* d_out, int out_size) {
    const float* x   = (const float*)d_in[0];
    const float* wg  = (const float*)d_in[1];
    const float* wgp = (const float*)d_in[2];
    const float* wup = (const float*)d_in[3];
    const float* wdp = (const float*)d_in[4];
    float* out = (float*)d_out;

    // lazy host-side stream/event setup (no device allocations; created on the
    // uncaptured correctness call, reused identically on every call thereafter)
    static cudaStream_t s1 = nullptr, s2 = nullptr;
    static cudaEvent_t  ev0 = nullptr, ev1 = nullptr, ev2 = nullptr;
    if (s1 == nullptr) {
        int lo = 0, hi = 0;
        cudaDeviceGetStreamPriorityRange(&lo, &hi);   // lo = LOWEST priority value
        cudaStreamCreateWithPriority(&s1, cudaStreamNonBlocking, lo);
        cudaStreamCreateWithPriority(&s2, cudaStreamNonBlocking, lo);
        cudaEventCreateWithFlags(&ev0, cudaEventDisableTiming);
        cudaEventCreateWithFlags(&ev1, cudaEventDisableTiming);
        cudaEventCreateWithFlags(&ev2, cudaEventDisableTiming);
    }

    cudaFuncSetAttribute(moe_gateup_kernel, cudaFuncAttributeMaxDynamicSharedMemorySize, SMEM_F);
    cudaFuncSetAttribute(moe_down_kernel,   cudaFuncAttributeMaxDynamicSharedMemorySize, SMEM_D);

    const int n4 = N_EXP * H_DIM * I_DIM / 4;

    // fork point
    cudaEventRecord(ev0, 0);

    // routing chain on the main stream (submitted first; short, latency-bound)
    zero_kernel<<<1, 32>>>();
    router_kernel<<<T_TOK / 8, 256>>>(x, wg);
    scan_kernel<<<1, 1>>>();
    assign_gather_kernel<<<T_TOK / 8, 256>>>(x);

    // weight splits + out-zero on low-priority streams (backfill)
    cudaStreamWaitEvent(s1, ev0, 0);
    split_w_gu<<<dim3(2048, 1, 2), 256, 0, s1>>>((const float4*)wgp, (const float4*)wup, n4);
    cudaEventRecord(ev1, s1);
    cudaStreamWaitEvent(s2, ev0, 0);
    zero_out_kernel<<<2048, 256, 0, s2>>>((float4*)out);
    split_w_d<<<2048, 256, 0, s2>>>((const float4*)wdp, n4);
    cudaEventRecord(ev2, s2);

    // join gate/up weights before gateup GEMM
    cudaStreamWaitEvent(0, ev1, 0);
    moe_gateup_kernel<<<dim3(I_DIM / 128, 272), 256, SMEM_F>>>();

    // join down weights + zeroed out before down GEMM (overlapped with gateup)
    cudaStreamWaitEvent(0, ev2, 0);
    moe_down_kernel<<<dim3(H_DIM / 128, 272), 256, SMEM_D>>>(out);
}